// round 3
// baseline (speedup 1.0000x reference)
#include <cuda_runtime.h>
#include <math.h>

#define IMG_W 256
#define IMG_H 256
#define GAB   4
#define MAXN  4096
#define SIGMA_T 30.0f
#define NTX 16
#define NTY 16
#define NTILES (NTX * NTY)
#define NBLK   NTILES
#define CAP 4096
#define MAXSORT 2048
#define SPLATS_PER_BLK 16

// Static scratch — no allocation. All zero at module load; every run restores zeros.
__device__ float4 d_geoA[2][MAXN];
__device__ float4 d_geoB[2][MAXN];
__device__ int d_cnt[NTILES];
__device__ unsigned short d_list[NTILES][CAP];
__device__ int d_arrive;
__device__ int d_done;

__global__ __launch_bounds__(256, 2)
void fused_kernel(const float* __restrict__ lmu, const float* __restrict__ lch,
                  const float* __restrict__ lft, const float* __restrict__ lop,
                  const float* __restrict__ hmu, const float* __restrict__ hch,
                  const float* __restrict__ hft, const float* __restrict__ hop,
                  const float* __restrict__ gfreq, const float* __restrict__ gwt,
                  int nl, int nh, float* __restrict__ out)
{
    __shared__ unsigned short sKey[MAXSORT];
    __shared__ unsigned short sSorted[MAXSORT];
    __shared__ float4 sA[128];
    __shared__ float4 sB[128];
    __shared__ float4 sF[128][2];
    __shared__ float4 sW[128];
    __shared__ unsigned short sK2[128];

    const int tid = threadIdx.x;
    const int blk = blockIdx.x;
    const int ntot = nl + nh;

    // ---------------- Phase A: prep + bin (threads 0..15 of each block) ----------------
    if (tid < SPLATS_PER_BLK) {
        int i = blk * SPLATS_PER_BLK + tid;
        if (i < ntot) {
            int slot, idx;
            const float *mu, *ch, *ft, *op;
            if (i < nl) { slot = 0; idx = i;      mu = lmu; ch = lch; ft = lft; op = lop; }
            else        { slot = 1; idx = i - nl; mu = hmu; ch = hch; ft = hft; op = hop; }

            float mx = tanhf(mu[idx * 2 + 0]);
            float my = tanhf(mu[idx * 2 + 1]);
            float x = (mx + 1.0f) * 0.5f * (float)IMG_W;
            float y = (my + 1.0f) * 0.5f * (float)IMG_H;

            float l1 = ch[idx * 3 + 0] + 0.5f;
            float l2 = ch[idx * 3 + 1];
            float l3 = ch[idx * 3 + 2] + 0.5f;
            float sxx = l1 * l1;
            float sxy = l1 * l2;
            float syy = l2 * l2 + l3 * l3;
            float det = sxx * syy - sxy * sxy;
            float c0 =  syy / det;
            float c1 = -sxy / det;
            float c2 =  sxx / det;

            float o = op[idx];

            float rx = sqrtf(fmaxf(2.0f * SIGMA_T * sxx, 0.0f)) + 0.01f;
            float ry = sqrtf(fmaxf(2.0f * SIGMA_T * syy, 0.0f)) + 0.01f;

            d_geoA[slot][idx] = make_float4(x, y, c0, c1);
            d_geoB[slot][idx] = make_float4(c2, o * ft[idx * 3 + 0],
                                            o * ft[idx * 3 + 1], o * ft[idx * 3 + 2]);

            float bxmin = x - rx, bxmax = x + rx;
            float bymin = y - ry, bymax = y + ry;
            int tx0 = max(0,       (int)ceilf ((bxmin - 15.5f) * (1.0f / 16.0f)));
            int tx1 = min(NTX - 1, (int)floorf((bxmax - 0.5f)  * (1.0f / 16.0f)));
            int ty0 = max(0,       (int)ceilf ((bymin - 15.5f) * (1.0f / 16.0f)));
            int ty1 = min(NTY - 1, (int)floorf((bymax - 0.5f)  * (1.0f / 16.0f)));

            unsigned short key = (unsigned short)((slot << 12) | idx);
            for (int ty = ty0; ty <= ty1; ty++)
                for (int tx = tx0; tx <= tx1; tx++) {
                    int t = ty * NTX + tx;
                    int s = atomicAdd(&d_cnt[t], 1);
                    if (s < CAP) d_list[t][s] = key;
                }
        }
    }

    // ---------------- Software grid barrier (all 256 CTAs co-resident: 148 SMs x 2) ----
    __threadfence();
    __syncthreads();
    if (tid == 0) {
        atomicAdd(&d_arrive, 1);
        while (*(volatile int*)&d_arrive < NBLK) { }
    }
    __syncthreads();
    __threadfence();

    // ---------------- Phase B: render own tile ----------------------------------------
    const int tx = blk & (NTX - 1), ty = blk >> 4;
    const int lx = tid & 15, ly = tid >> 4;
    const float px = (float)(tx * 16 + lx) + 0.5f;
    const float py = (float)(ty * 16 + ly) + 0.5f;

    int cnt = d_cnt[blk];
    cnt = min(cnt, CAP);
    cnt = min(cnt, MAXSORT);

    for (int e = tid; e < cnt; e += 256) sKey[e] = d_list[blk][e];
    __syncthreads();

    if (tid == 0) d_cnt[blk] = 0;   // restore state for next graph replay

    // Deterministic order: rank-sort unique keys (low-pass first, ascending idx)
    for (int e = tid; e < cnt; e += 256) {
        unsigned short k = sKey[e];
        int rank = 0;
        for (int j = 0; j < cnt; j++) rank += (sKey[j] < k);
        sSorted[rank] = k;
    }
    __syncthreads();

    float ar = 0.0f, ag = 0.0f, ab = 0.0f;

    for (int base = 0; base < cnt; base += 128) {
        const int m = min(128, cnt - base);
        if (tid < m) {
            unsigned short k = sSorted[base + tid];
            int pass = k >> 12;
            int idx  = k & 0xFFF;
            sK2[tid] = k;
            sA[tid] = d_geoA[pass][idx];
            sB[tid] = d_geoB[pass][idx];
            if (pass) {
                const float2* f2 = (const float2*)gfreq;
                float2 f0 = f2[idx * GAB + 0];
                float2 f1 = f2[idx * GAB + 1];
                float2 f2v = f2[idx * GAB + 2];
                float2 f3 = f2[idx * GAB + 3];
                sF[tid][0] = make_float4(f0.x, f0.y, f1.x, f1.y);
                sF[tid][1] = make_float4(f2v.x, f2v.y, f3.x, f3.y);
                sW[tid] = make_float4(gwt[idx * GAB + 0], gwt[idx * GAB + 1],
                                      gwt[idx * GAB + 2], gwt[idx * GAB + 3]);
            }
        }
        __syncthreads();

        for (int j = 0; j < m; j++) {
            float4 A = sA[j], B = sB[j];
            float dx = px - A.x, dy = py - A.y;
            float sig = 0.5f * A.z * dx * dx + A.w * dx * dy + 0.5f * B.x * dy * dy;
            float w = __expf(-sig);
            if (sK2[j] >> 12) {
                float4 F0 = sF[j][0], F1 = sF[j][1], Wt = sW[j];
                float mod = Wt.x * __cosf(F0.x * dx + F0.y * dy)
                          + Wt.y * __cosf(F0.z * dx + F0.w * dy)
                          + Wt.z * __cosf(F1.x * dx + F1.y * dy)
                          + Wt.w * __cosf(F1.z * dx + F1.w * dy);
                w *= mod;
            }
            ar += w * B.y; ag += w * B.z; ab += w * B.w;
        }
        __syncthreads();
    }

    const int pix = (ty * 16 + ly) * IMG_W + tx * 16 + lx;
    out[pix]                     = fminf(fmaxf(ar, 0.0f), 1.0f);
    out[IMG_H * IMG_W + pix]     = fminf(fmaxf(ag, 0.0f), 1.0f);
    out[2 * IMG_H * IMG_W + pix] = fminf(fmaxf(ab, 0.0f), 1.0f);

    // ---------------- Restore barrier counters (last block out resets) -----------------
    if (tid == 0) {
        __threadfence();
        int v = atomicAdd(&d_done, 1);
        if (v == NBLK - 1) {
            d_arrive = 0;
            d_done = 0;
            __threadfence();
        }
    }
}

extern "C" void kernel_launch(void* const* d_in, const int* in_sizes, int n_in,
                              void* d_out, int out_size)
{
    const float* low_mu    = (const float*)d_in[0];
    const float* high_mu   = (const float*)d_in[1];
    const float* low_chol  = (const float*)d_in[2];
    const float* high_chol = (const float*)d_in[3];
    const float* low_feat  = (const float*)d_in[4];
    const float* high_feat = (const float*)d_in[5];
    const float* low_opac  = (const float*)d_in[6];
    const float* high_opac = (const float*)d_in[7];
    const float* gfreq     = (const float*)d_in[8];
    const float* gwt       = (const float*)d_in[9];

    const int nl = in_sizes[6];
    const int nh = in_sizes[7];

    fused_kernel<<<NBLK, 256>>>(low_mu, low_chol, low_feat, low_opac,
                                high_mu, high_chol, high_feat, high_opac,
                                gfreq, gwt, nl, nh, (float*)d_out);
}

// round 4
// speedup vs baseline: 1.3409x; 1.3409x over previous
#include <cuda_runtime.h>
#include <math.h>

#define IMG_W 256
#define IMG_H 256
#define NPIX  (IMG_W * IMG_H)
#define GAB   4
#define NBLK  256
#define NTHR  256
#define NWARP (NBLK * (NTHR / 32))
#define TCUT  12.0f

// Static scratch — zero at module load; kernel restores zeros each run.
__device__ float d_acc[3 * NPIX];
__device__ int d_arrive;
__device__ int d_done;

__global__ __launch_bounds__(NTHR, 2)
void fused_splat_kernel(const float* __restrict__ lmu, const float* __restrict__ lch,
                        const float* __restrict__ lft, const float* __restrict__ lop,
                        const float* __restrict__ hmu, const float* __restrict__ hch,
                        const float* __restrict__ hft, const float* __restrict__ hop,
                        const float* __restrict__ gfreq, const float* __restrict__ gwt,
                        int nl, int nh, float* __restrict__ out)
{
    const int tid  = threadIdx.x;
    const int blk  = blockIdx.x;
    const int gtid = blk * NTHR + tid;
    const int lane = tid & 31;
    const int gw   = blk * (NTHR / 32) + (tid >> 5);
    const int ntot = nl + nh;

    // ---------------- Phase 1: one warp per splat, scatter into d_acc ----------------
    for (int s = gw; s < ntot; s += NWARP) {
        int slot, idx;
        const float *mu, *ch, *ft, *op;
        if (s < nl) { slot = 0; idx = s;      mu = lmu; ch = lch; ft = lft; op = lop; }
        else        { slot = 1; idx = s - nl; mu = hmu; ch = hch; ft = hft; op = hop; }

        // All lanes load the same addresses (broadcast) and redo the cheap prep.
        float x = (tanhf(mu[idx * 2 + 0]) + 1.0f) * 0.5f * (float)IMG_W;
        float y = (tanhf(mu[idx * 2 + 1]) + 1.0f) * 0.5f * (float)IMG_H;

        float l1 = ch[idx * 3 + 0] + 0.5f;
        float l2 = ch[idx * 3 + 1];
        float l3 = ch[idx * 3 + 2] + 0.5f;
        float sxx = l1 * l1;
        float sxy = l1 * l2;
        float syy = l2 * l2 + l3 * l3;
        float det = sxx * syy - sxy * sxy;
        float c0 =  syy / det;
        float c1 = -sxy / det;
        float c2 =  sxx / det;

        float o  = op[idx];
        float cr = o * ft[idx * 3 + 0];
        float cg = o * ft[idx * 3 + 1];
        float cb = o * ft[idx * 3 + 2];

        float rx = sqrtf(fmaxf(2.0f * TCUT * sxx, 0.0f)) + 0.01f;
        float ry = sqrtf(fmaxf(2.0f * TCUT * syy, 0.0f)) + 0.01f;

        int x0 = max(0,         (int)ceilf (x - rx - 0.5f));
        int x1 = min(IMG_W - 1, (int)floorf(x + rx - 0.5f));
        int y0 = max(0,         (int)ceilf (y - ry - 0.5f));
        int y1 = min(IMG_H - 1, (int)floorf(y + ry - 0.5f));
        if (x0 > x1 || y0 > y1) continue;

        // Gabor params (warp-uniform)
        float f0x = 0, f0y = 0, f1x = 0, f1y = 0, f2x = 0, f2y = 0, f3x = 0, f3y = 0;
        float w0 = 0, w1 = 0, w2 = 0, w3 = 0;
        if (slot) {
            const float* fq = gfreq + (size_t)idx * GAB * 2;
            f0x = fq[0]; f0y = fq[1]; f1x = fq[2]; f1y = fq[3];
            f2x = fq[4]; f2y = fq[5]; f3x = fq[6]; f3y = fq[7];
            const float* wq = gwt + (size_t)idx * GAB;
            w0 = wq[0]; w1 = wq[1]; w2 = wq[2]; w3 = wq[3];
        }

        int Wd = x1 - x0 + 1;
        int A  = Wd * (y1 - y0 + 1);
        for (int p = lane; p < A; p += 32) {
            int ryi = p / Wd;
            int rxi = p - ryi * Wd;
            int pxi = x0 + rxi;
            int pyi = y0 + ryi;
            float dx = (float)pxi + 0.5f - x;
            float dy = (float)pyi + 0.5f - y;
            float sig = 0.5f * c0 * dx * dx + c1 * dx * dy + 0.5f * c2 * dy * dy;
            if (sig <= TCUT) {
                float w = __expf(-sig);
                if (slot) {
                    float mod = w0 * __cosf(f0x * dx + f0y * dy)
                              + w1 * __cosf(f1x * dx + f1y * dy)
                              + w2 * __cosf(f2x * dx + f2y * dy)
                              + w3 * __cosf(f3x * dx + f3y * dy);
                    w *= mod;
                }
                int pix = pyi * IMG_W + pxi;
                atomicAdd(&d_acc[pix],            w * cr);
                atomicAdd(&d_acc[NPIX + pix],     w * cg);
                atomicAdd(&d_acc[2 * NPIX + pix], w * cb);
            }
        }
    }

    // ---------------- Grid barrier (256 CTAs co-resident; regs/smem allow >=2/SM) -----
    __threadfence();
    __syncthreads();
    if (tid == 0) {
        atomicAdd(&d_arrive, 1);
        while (*(volatile int*)&d_arrive < NBLK) { }
    }
    __syncthreads();
    __threadfence();

    // ---------------- Phase 2: clip -> out, and restore d_acc to zero ----------------
    {
        const int nvec = (3 * NPIX) / 4;   // 49152 float4
        float4* acc4 = (float4*)d_acc;
        float4* out4 = (float4*)out;
        for (int v = gtid; v < nvec; v += NBLK * NTHR) {
            float4 a = acc4[v];
            acc4[v] = make_float4(0.f, 0.f, 0.f, 0.f);
            a.x = fminf(fmaxf(a.x, 0.f), 1.f);
            a.y = fminf(fmaxf(a.y, 0.f), 1.f);
            a.z = fminf(fmaxf(a.z, 0.f), 1.f);
            a.w = fminf(fmaxf(a.w, 0.f), 1.f);
            out4[v] = a;
        }
    }

    // ---------------- Reset barrier counters (last block out) ------------------------
    if (tid == 0) {
        __threadfence();
        int v = atomicAdd(&d_done, 1);
        if (v == NBLK - 1) {
            d_arrive = 0;
            d_done = 0;
            __threadfence();
        }
    }
}

extern "C" void kernel_launch(void* const* d_in, const int* in_sizes, int n_in,
                              void* d_out, int out_size)
{
    const float* low_mu    = (const float*)d_in[0];
    const float* high_mu   = (const float*)d_in[1];
    const float* low_chol  = (const float*)d_in[2];
    const float* high_chol = (const float*)d_in[3];
    const float* low_feat  = (const float*)d_in[4];
    const float* high_feat = (const float*)d_in[5];
    const float* low_opac  = (const float*)d_in[6];
    const float* high_opac = (const float*)d_in[7];
    const float* gfreq     = (const float*)d_in[8];
    const float* gwt       = (const float*)d_in[9];

    const int nl = in_sizes[6];
    const int nh = in_sizes[7];

    fused_splat_kernel<<<NBLK, NTHR>>>(low_mu, low_chol, low_feat, low_opac,
                                       high_mu, high_chol, high_feat, high_opac,
                                       gfreq, gwt, nl, nh, (float*)d_out);
}

// round 6
// speedup vs baseline: 1.4459x; 1.0784x over previous
#include <cuda_runtime.h>
#include <math.h>

#define IMG_W 256
#define IMG_H 256
#define NPIX  (IMG_W * IMG_H)
#define GAB   4
#define NBLK  256
#define NTHR  256
#define NWARP (NBLK * (NTHR / 32))
#define TCUT  10.0f

// Static scratch — zero at module load; kernel restores zeros each run.
__device__ float d_acc[3 * NPIX];
__device__ int d_cnt32[32];
__device__ int d_done;

__global__ __launch_bounds__(NTHR, 2)
void fused_splat_kernel(const float* __restrict__ lmu, const float* __restrict__ lch,
                        const float* __restrict__ lft, const float* __restrict__ lop,
                        const float* __restrict__ hmu, const float* __restrict__ hch,
                        const float* __restrict__ hft, const float* __restrict__ hop,
                        const float* __restrict__ gfreq, const float* __restrict__ gwt,
                        int nl, int nh, float* __restrict__ out)
{
    const int tid   = threadIdx.x;
    const int blk   = blockIdx.x;
    const int gtid  = blk * NTHR + tid;
    const int lane  = tid & 31;
    const int half  = lane >> 4;        // 0 or 1: which splat of the pair
    const int hlane = lane & 15;        // lane within half-warp
    const int gw    = blk * (NTHR / 32) + (tid >> 5);
    const int ntot  = nl + nh;

    // ------------- Phase 1: half-warp per splat (adjacent pairing), scatter -------------
    for (int sb = gw * 2; sb < ntot; sb += 2 * NWARP) {
        int s = sb + half;
        bool valid = (s < ntot);
        if (valid) {
            int slot, idx;
            const float *mu, *ch, *ft, *op;
            if (s < nl) { slot = 0; idx = s;      mu = lmu; ch = lch; ft = lft; op = lop; }
            else        { slot = 1; idx = s - nl; mu = hmu; ch = hch; ft = hft; op = hop; }

            float x = (tanhf(mu[idx * 2 + 0]) + 1.0f) * 0.5f * (float)IMG_W;
            float y = (tanhf(mu[idx * 2 + 1]) + 1.0f) * 0.5f * (float)IMG_H;

            float l1 = ch[idx * 3 + 0] + 0.5f;
            float l2 = ch[idx * 3 + 1];
            float l3 = ch[idx * 3 + 2] + 0.5f;
            float sxx = l1 * l1;
            float sxy = l1 * l2;
            float syy = l2 * l2 + l3 * l3;
            float det = sxx * syy - sxy * sxy;
            float inv = 1.0f / det;
            float c0 =  syy * inv;
            float c1 = -sxy * inv;
            float c2 =  sxx * inv;

            float o  = op[idx];
            float cr = o * ft[idx * 3 + 0];
            float cg = o * ft[idx * 3 + 1];
            float cb = o * ft[idx * 3 + 2];

            float rx = sqrtf(fmaxf(2.0f * TCUT * sxx, 0.0f)) + 0.01f;
            float ry = sqrtf(fmaxf(2.0f * TCUT * syy, 0.0f)) + 0.01f;

            int x0 = max(0,         (int)ceilf (x - rx - 0.5f));
            int x1 = min(IMG_W - 1, (int)floorf(x + rx - 0.5f));
            int y0 = max(0,         (int)ceilf (y - ry - 0.5f));
            int y1 = min(IMG_H - 1, (int)floorf(y + ry - 0.5f));

            if (x0 <= x1 && y0 <= y1) {
                float f0x = 0, f0y = 0, f1x = 0, f1y = 0;
                float f2x = 0, f2y = 0, f3x = 0, f3y = 0;
                float w0 = 0, w1 = 0, w2 = 0, w3 = 0;
                if (slot) {
                    const float* fq = gfreq + (size_t)idx * GAB * 2;
                    f0x = fq[0]; f0y = fq[1]; f1x = fq[2]; f1y = fq[3];
                    f2x = fq[4]; f2y = fq[5]; f3x = fq[6]; f3y = fq[7];
                    const float* wq = gwt + (size_t)idx * GAB;
                    w0 = wq[0]; w1 = wq[1]; w2 = wq[2]; w3 = wq[3];
                }

                int Wd = x1 - x0 + 1;
                int A  = Wd * (y1 - y0 + 1);
                for (int p = hlane; p < A; p += 16) {
                    int ryi = p / Wd;
                    int rxi = p - ryi * Wd;
                    int pxi = x0 + rxi;
                    int pyi = y0 + ryi;
                    float dx = (float)pxi + 0.5f - x;
                    float dy = (float)pyi + 0.5f - y;
                    float sig = 0.5f * c0 * dx * dx + c1 * dx * dy + 0.5f * c2 * dy * dy;
                    if (sig <= TCUT) {
                        float w = __expf(-sig);
                        if (slot) {
                            float mod = w0 * __cosf(f0x * dx + f0y * dy)
                                      + w1 * __cosf(f1x * dx + f1y * dy)
                                      + w2 * __cosf(f2x * dx + f2y * dy)
                                      + w3 * __cosf(f3x * dx + f3y * dy);
                            w *= mod;
                        }
                        int pix = pyi * IMG_W + pxi;
                        atomicAdd(&d_acc[pix],            w * cr);
                        atomicAdd(&d_acc[NPIX + pix],     w * cg);
                        atomicAdd(&d_acc[2 * NPIX + pix], w * cb);
                    }
                }
            }
        }
    }

    // ------------- Grid barrier: 32 distributed counters, lane-parallel poll ------------
    __threadfence();
    __syncthreads();
    if (tid == 0) {
        atomicAdd(&d_cnt32[blk & 31], 1);
    }
    if (tid < 32) {
        int sum;
        do {
            int v = *(volatile int*)&d_cnt32[lane];
            sum = __reduce_add_sync(0xffffffffu, v);
        } while (sum < NBLK);
    }
    __syncthreads();
    __threadfence();

    // ------------- Phase 2: clip -> out, restore d_acc to zero --------------------------
    {
        const int nvec = (3 * NPIX) / 4;   // 49152 float4
        float4* acc4 = (float4*)d_acc;
        float4* out4 = (float4*)out;
        for (int v = gtid; v < nvec; v += NBLK * NTHR) {
            float4 a = acc4[v];
            acc4[v] = make_float4(0.f, 0.f, 0.f, 0.f);
            a.x = fminf(fmaxf(a.x, 0.f), 1.f);
            a.y = fminf(fmaxf(a.y, 0.f), 1.f);
            a.z = fminf(fmaxf(a.z, 0.f), 1.f);
            a.w = fminf(fmaxf(a.w, 0.f), 1.f);
            out4[v] = a;
        }
    }

    // ------------- Reset barrier counters (last CTA out) --------------------------------
    if (tid == 0) {
        __threadfence();
        int v = atomicAdd(&d_done, 1);
        if (v == NBLK - 1) {
            #pragma unroll
            for (int i = 0; i < 32; i++) d_cnt32[i] = 0;
            d_done = 0;
            __threadfence();
        }
    }
}

extern "C" void kernel_launch(void* const* d_in, const int* in_sizes, int n_in,
                              void* d_out, int out_size)
{
    const float* low_mu    = (const float*)d_in[0];
    const float* high_mu   = (const float*)d_in[1];
    const float* low_chol  = (const float*)d_in[2];
    const float* high_chol = (const float*)d_in[3];
    const float* low_feat  = (const float*)d_in[4];
    const float* high_feat = (const float*)d_in[5];
    const float* low_opac  = (const float*)d_in[6];
    const float* high_opac = (const float*)d_in[7];
    const float* gfreq     = (const float*)d_in[8];
    const float* gwt       = (const float*)d_in[9];

    const int nl = in_sizes[6];
    const int nh = in_sizes[7];

    fused_splat_kernel<<<NBLK, NTHR>>>(low_mu, low_chol, low_feat, low_opac,
                                       high_mu, high_chol, high_feat, high_opac,
                                       gfreq, gwt, nl, nh, (float*)d_out);
}

// round 8
// speedup vs baseline: 1.5923x; 1.1012x over previous
#include <cuda_runtime.h>
#include <math.h>

#define IMG_W 256
#define IMG_H 256
#define NPIX  (IMG_W * IMG_H)
#define GAB   4
#define NBLK  256
#define NTHR  256
#define NWARP (NBLK * (NTHR / 32))   // 2048
#define TCUT  10.0f

// Static scratch — zero at module load; kernel restores zeros each run.
__device__ float4 d_acc[NPIX];       // RGBA accumulator (A unused)
__device__ int d_cnt32[32];
__device__ int d_done;

__device__ __forceinline__ void red_add_v4(float4* addr, float r, float g, float b)
{
    asm volatile("red.global.add.v4.f32 [%0], {%1, %2, %3, %4};"
                 :: "l"(addr), "f"(r), "f"(g), "f"(b), "f"(0.0f)
                 : "memory");
}

__global__ __launch_bounds__(NTHR, 2)
void fused_splat_kernel(const float* __restrict__ lmu, const float* __restrict__ lch,
                        const float* __restrict__ lft, const float* __restrict__ lop,
                        const float* __restrict__ hmu, const float* __restrict__ hch,
                        const float* __restrict__ hft, const float* __restrict__ hop,
                        const float* __restrict__ gfreq, const float* __restrict__ gwt,
                        int nl, int nh, float* __restrict__ out)
{
    const int tid   = threadIdx.x;
    const int blk   = blockIdx.x;
    const int gtid  = blk * NTHR + tid;
    const int lane  = tid & 31;
    const int half  = lane >> 4;
    const int hlane = lane & 15;
    const int gw    = blk * (NTHR / 32) + (tid >> 5);
    const int ntot  = nl + nh;
    const int npairs = (ntot + 1) >> 1;

    // Permuted pair id: spreads the heavy (gabor) tail pairs across all CTAs.
    const int pid0 = ((gw & 7) << 8) | (gw >> 3);

    // ------------- Phase 1: half-warp per splat (adjacent same-type pairs) -------------
    for (int pid = pid0; pid < npairs; pid += NWARP) {
        int s = pid * 2 + half;
        if (s < ntot) {
            int slot, idx;
            const float *mu, *ch, *ft, *op;
            if (s < nl) { slot = 0; idx = s;      mu = lmu; ch = lch; ft = lft; op = lop; }
            else        { slot = 1; idx = s - nl; mu = hmu; ch = hch; ft = hft; op = hop; }

            float x = (tanhf(mu[idx * 2 + 0]) + 1.0f) * 0.5f * (float)IMG_W;
            float y = (tanhf(mu[idx * 2 + 1]) + 1.0f) * 0.5f * (float)IMG_H;

            float l1 = ch[idx * 3 + 0] + 0.5f;
            float l2 = ch[idx * 3 + 1];
            float l3 = ch[idx * 3 + 2] + 0.5f;
            float sxx = l1 * l1;
            float sxy = l1 * l2;
            float syy = l2 * l2 + l3 * l3;
            float det = sxx * syy - sxy * sxy;
            float inv = 1.0f / det;
            float c0 =  syy * inv;
            float c1 = -sxy * inv;
            float c2 =  sxx * inv;

            float o  = op[idx];
            float cr = o * ft[idx * 3 + 0];
            float cg = o * ft[idx * 3 + 1];
            float cb = o * ft[idx * 3 + 2];

            float rx = sqrtf(fmaxf(2.0f * TCUT * sxx, 0.0f)) + 0.01f;
            float ry = sqrtf(fmaxf(2.0f * TCUT * syy, 0.0f)) + 0.01f;

            int x0 = max(0,         (int)ceilf (x - rx - 0.5f));
            int x1 = min(IMG_W - 1, (int)floorf(x + rx - 0.5f));
            int y0 = max(0,         (int)ceilf (y - ry - 0.5f));
            int y1 = min(IMG_H - 1, (int)floorf(y + ry - 0.5f));

            if (x0 <= x1 && y0 <= y1) {
                float f0x = 0, f0y = 0, f1x = 0, f1y = 0;
                float f2x = 0, f2y = 0, f3x = 0, f3y = 0;
                float w0 = 0, w1 = 0, w2 = 0, w3 = 0;
                if (slot) {
                    const float* fq = gfreq + (size_t)idx * GAB * 2;
                    f0x = fq[0]; f0y = fq[1]; f1x = fq[2]; f1y = fq[3];
                    f2x = fq[4]; f2y = fq[5]; f3x = fq[6]; f3y = fq[7];
                    const float* wq = gwt + (size_t)idx * GAB;
                    w0 = wq[0]; w1 = wq[1]; w2 = wq[2]; w3 = wq[3];
                }

                int Wd = x1 - x0 + 1;
                int A  = Wd * (y1 - y0 + 1);
                for (int p = hlane; p < A; p += 16) {
                    int ryi = p / Wd;
                    int rxi = p - ryi * Wd;
                    int pxi = x0 + rxi;
                    int pyi = y0 + ryi;
                    float dx = (float)pxi + 0.5f - x;
                    float dy = (float)pyi + 0.5f - y;
                    float sig = 0.5f * c0 * dx * dx + c1 * dx * dy + 0.5f * c2 * dy * dy;
                    if (sig <= TCUT) {
                        float w = __expf(-sig);
                        if (slot) {
                            float mod = w0 * __cosf(f0x * dx + f0y * dy)
                                      + w1 * __cosf(f1x * dx + f1y * dy)
                                      + w2 * __cosf(f2x * dx + f2y * dy)
                                      + w3 * __cosf(f3x * dx + f3y * dy);
                            w *= mod;
                        }
                        red_add_v4(&d_acc[pyi * IMG_W + pxi], w * cr, w * cg, w * cb);
                    }
                }
            }
        }
    }

    // ------------- Grid barrier: 32 distributed counters, lane-parallel poll ------------
    __threadfence();
    __syncthreads();
    if (tid == 0) {
        atomicAdd(&d_cnt32[blk & 31], 1);
    }
    if (tid < 32) {
        int sum;
        do {
            int v = *(volatile int*)&d_cnt32[lane];
            sum = __reduce_add_sync(0xffffffffu, v);
        } while (sum < NBLK);
    }
    __syncthreads();
    __threadfence();

    // ------------- Phase 2: one pixel per thread: clip -> planar out, re-zero -----------
    {
        float4 a = d_acc[gtid];
        d_acc[gtid] = make_float4(0.f, 0.f, 0.f, 0.f);
        out[gtid]            = fminf(fmaxf(a.x, 0.f), 1.f);
        out[NPIX + gtid]     = fminf(fmaxf(a.y, 0.f), 1.f);
        out[2 * NPIX + gtid] = fminf(fmaxf(a.z, 0.f), 1.f);
    }

    // ------------- Reset barrier counters (last CTA out) --------------------------------
    if (tid == 0) {
        __threadfence();
        int v = atomicAdd(&d_done, 1);
        if (v == NBLK - 1) {
            #pragma unroll
            for (int i = 0; i < 32; i++) d_cnt32[i] = 0;
            d_done = 0;
            __threadfence();
        }
    }
}

extern "C" void kernel_launch(void* const* d_in, const int* in_sizes, int n_in,
                              void* d_out, int out_size)
{
    const float* low_mu    = (const float*)d_in[0];
    const float* high_mu   = (const float*)d_in[1];
    const float* low_chol  = (const float*)d_in[2];
    const float* high_chol = (const float*)d_in[3];
    const float* low_feat  = (const float*)d_in[4];
    const float* high_feat = (const float*)d_in[5];
    const float* low_opac  = (const float*)d_in[6];
    const float* high_opac = (const float*)d_in[7];
    const float* gfreq     = (const float*)d_in[8];
    const float* gwt       = (const float*)d_in[9];

    const int nl = in_sizes[6];
    const int nh = in_sizes[7];

    fused_splat_kernel<<<NBLK, NTHR>>>(low_mu, low_chol, low_feat, low_opac,
                                       high_mu, high_chol, high_feat, high_opac,
                                       gfreq, gwt, nl, nh, (float*)d_out);
}